// round 6
// baseline (speedup 1.0000x reference)
#include <cuda_runtime.h>
#include <math.h>

#define KD 64
#define MDIM 256
#define VDIM 5000
#define LMBDA 0.001f
#define NITER 6
#define VCHUNK 200
#define KSPLIT 25
#define SH2 68     // staging stride (floats)
#define SRV 132    // VsT stride (floats)

// ---------------- device scratch ----------------
__device__ float g_AP[2][KD * MDIM];     // [0]=A=tx@fx, [1]=Py=ty@fy
__device__ float g_S[KD * KD];           // inv(sx)
__device__ float g_Sy[KD * KD];          // inv(sy)
__device__ float g_H[KD * KD];           // sy^T sy
__device__ float g_G[KD * KD];           // A A^T
__device__ float g_T1[KD * KD];          // Py A^T
__device__ float g_Mcat[KD * 192];       // [M2 | M1 | M0]
__device__ float g_NT[192 * KD];         // transposed [N2;N1;N0], NT[j][k]=N[k][j]
__device__ float g_Hinv[KD * KD];
__device__ float g_Ginv[KD * KD];
__device__ float g_HL[KD * KD];          // H ly + ly H   (symmetric)
__device__ float g_LHL[KD * KD];         // ly H ly       (symmetric)
__device__ float g_LP[KD * 128];         // [-Hinv HL | Hinv LHL]
__device__ float g_X0[KD * KD];
__device__ float g_V[2][KD * 192];       // double-buffered X @ Ncat
__device__ int   g_flags[32];
// flag indices:
// 0,1: gemm done count per mat (target 100)
// 2: f_S  3: f_Sy  4: f_HL  5: f_Hinv
// 6: c_G (4)  7: c_T1 (4)  8..10: f_M[j]  11: f_Ginv  12: c_N (3)  13: c_LP (2)
// 16+it: per-iteration barrier (target 4)

// ---------------- sync helpers ----------------
__device__ __forceinline__ void waitflag(int idx, int target) {
  if (threadIdx.x == 0) {
    while (((volatile int*)g_flags)[idx] < target) { }
  }
  __syncthreads();
}
__device__ __forceinline__ void signalflag(int idx) {
  __threadfence();
  __syncthreads();
  if (threadIdx.x == 0) atomicAdd(&g_flags[idx], 1);
}

// ---------------- helpers ----------------

// C[a0..a0+15][0..63] = scale * sum_k P[a][k]*Q[b][k]; strides multiples of 4.
__device__ __forceinline__ void mm_nt_16(
    const float* __restrict__ P, int ldp,
    const float* __restrict__ Q, int ldq,
    int Klen, float* __restrict__ C, int ldc, int a0, float scale) {
  const int tid = threadIdx.x;
  const int a = a0 + (tid >> 4);
  const int b0 = (tid & 15) << 2;
  float acc0 = 0.f, acc1 = 0.f, acc2 = 0.f, acc3 = 0.f;
  const float4* Pr = (const float4*)(P + a * ldp);
  const float4* Q0 = (const float4*)(Q + (b0 + 0) * ldq);
  const float4* Q1 = (const float4*)(Q + (b0 + 1) * ldq);
  const float4* Q2 = (const float4*)(Q + (b0 + 2) * ldq);
  const float4* Q3 = (const float4*)(Q + (b0 + 3) * ldq);
  const int k4 = Klen >> 2;
  for (int k = 0; k < k4; k++) {
    float4 av = Pr[k];
    float4 bv;
    bv = Q0[k]; acc0 += av.x * bv.x + av.y * bv.y + av.z * bv.z + av.w * bv.w;
    bv = Q1[k]; acc1 += av.x * bv.x + av.y * bv.y + av.z * bv.z + av.w * bv.w;
    bv = Q2[k]; acc2 += av.x * bv.x + av.y * bv.y + av.z * bv.z + av.w * bv.w;
    bv = Q3[k]; acc3 += av.x * bv.x + av.y * bv.y + av.z * bv.z + av.w * bv.w;
  }
  float* Cr = C + a * ldc + b0;
  Cr[0] = acc0 * scale; Cr[1] = acc1 * scale;
  Cr[2] = acc2 * scale; Cr[3] = acc3 * scale;
}

// Register-resident pivot-free Gauss-Jordan inverse of a 64x64 (inputs SPD or
// near-identity). 256 threads; thread owns column c=tid&63, rows r0+4q.
// Pipelined: next pivot's row/col published in same phase -> 1 barrier/pivot.
__device__ void gj_inverse_reg(const float* __restrict__ in,
                               float* __restrict__ out) {
  __shared__ float prow[2][64];
  __shared__ float pcol[2][64];
  const int tid = threadIdx.x;
  const int r0 = tid >> 6;        // 0..3
  const int c  = tid & 63;
  float v[16];
#pragma unroll
  for (int q = 0; q < 16; q++) v[q] = in[(r0 + 4 * q) * 64 + c];
  // publish pivot 0 (pre-update values)
  if (c == 0) {
#pragma unroll
    for (int q = 0; q < 16; q++) pcol[0][r0 + 4 * q] = v[q];
  }
  if (r0 == 0) prow[0][c] = v[0];
  __syncthreads();
  for (int p = 0; p < 64; p++) {
    const int cur = p & 1, nxt = cur ^ 1;
    const float dinv = 1.0f / prow[cur][p];
    const float prc = prow[cur][c] * dinv;
    if (c == p) {
#pragma unroll
      for (int q = 0; q < 16; q++) {
        int r = r0 + 4 * q;
        v[q] = (r == p) ? dinv : -v[q] * dinv;
      }
    } else {
#pragma unroll
      for (int q = 0; q < 16; q++) {
        int r = r0 + 4 * q;
        v[q] = (r == p) ? prc : fmaf(-pcol[cur][r], prc, v[q]);
      }
    }
    if (p < 63) {
      const int pn = p + 1;
      if (c == pn) {
#pragma unroll
        for (int q = 0; q < 16; q++) pcol[nxt][r0 + 4 * q] = v[q];
      }
      if (r0 == (pn & 3)) prow[nxt][c] = v[pn >> 2];
    }
    __syncthreads();
  }
#pragma unroll
  for (int q = 0; q < 16; q++) out[(r0 + 4 * q) * 64 + c] = v[q];
}

// ---------------- kernels ----------------

__global__ void reset_kernel() {
  const int b = blockIdx.x, tid = threadIdx.x;
  if (b < 32) {
    ((float4*)g_AP)[b * 256 + tid] = make_float4(0.f, 0.f, 0.f, 0.f);
  } else {
    if (tid < 32) g_flags[tid] = 0;
  }
}

__global__ void __launch_bounds__(256, 3) mega_kernel(
    const float* __restrict__ fx, const float* __restrict__ fy,
    const float* __restrict__ ex, const float* __restrict__ ey,
    const float* __restrict__ tx, const float* __restrict__ ty,
    const float* __restrict__ sx, const float* __restrict__ sy,
    float* __restrict__ outp) {
  __shared__ __align__(16) float sh[64 * SRV];   // 8448 floats, multi-use
  const int bid = blockIdx.x;
  const int tid = threadIdx.x;

  if (bid < 200) {
    // ---- gemm: A = tx@fx (mat 0), Py = ty@fy (mat 1), split-K atomics ----
    const int mat = bid / 100;
    const int r   = bid % 100;
    const int mt  = r & 3;
    const int vs  = r >> 2;
    const float* __restrict__ F  = mat ? fy : fx;   // [VDIM][MDIM]
    const float* __restrict__ Wm = mat ? ty : tx;   // [KD][VDIM]
    float* out = g_AP[mat];
    const int m0 = mt * 64;
    const int v0 = vs * VCHUNK;
    float* Ws = sh;          // [8][64]
    float* Fs = sh + 512;    // [8][64]
    const int tr = (tid >> 4) << 2;
    const int tc = (tid & 15) << 2;
    float acc[4][4];
#pragma unroll
    for (int i = 0; i < 4; i++)
#pragma unroll
      for (int j = 0; j < 4; j++) acc[i][j] = 0.f;
    for (int vv = v0; vv < v0 + VCHUNK; vv += 8) {
      int idx = tid;
#pragma unroll
      for (int q = 0; q < 2; q++, idx += 256) {
        int kk = idx & 7, row = idx >> 3;
        Ws[kk * 64 + row] = Wm[row * VDIM + vv + kk];
        int kk2 = idx >> 6, col = idx & 63;
        Fs[kk2 * 64 + col] = F[(vv + kk2) * MDIM + m0 + col];
      }
      __syncthreads();
#pragma unroll
      for (int kk = 0; kk < 8; kk++) {
        float4 av = *(const float4*)&Ws[kk * 64 + tr];
        float4 bv = *(const float4*)&Fs[kk * 64 + tc];
        acc[0][0] += av.x * bv.x; acc[0][1] += av.x * bv.y; acc[0][2] += av.x * bv.z; acc[0][3] += av.x * bv.w;
        acc[1][0] += av.y * bv.x; acc[1][1] += av.y * bv.y; acc[1][2] += av.y * bv.z; acc[1][3] += av.y * bv.w;
        acc[2][0] += av.z * bv.x; acc[2][1] += av.z * bv.y; acc[2][2] += av.z * bv.z; acc[2][3] += av.z * bv.w;
        acc[3][0] += av.w * bv.x; acc[3][1] += av.w * bv.y; acc[3][2] += av.w * bv.z; acc[3][3] += av.w * bv.w;
      }
      __syncthreads();
    }
#pragma unroll
    for (int i = 0; i < 4; i++)
#pragma unroll
      for (int j = 0; j < 4; j++)
        atomicAdd(&out[(tr + i) * MDIM + m0 + tc + j], acc[i][j]);
    signalflag(mat);

  } else if (bid == 200) {
    // ---- S = inv(sx) ----
    gj_inverse_reg(sx, g_S);
    signalflag(2);

  } else if (bid == 201) {
    // ---- Sy = inv(sy) ----
    gj_inverse_reg(sy, g_Sy);
    signalflag(3);

  } else if (bid == 202) {
    // ---- H = sy^T sy, then HL = H.*(ey_r+ey_c), LHL = ey_r.*H.*ey_c ----
    for (int i = tid; i < 4096; i += 256) {
      int a = i >> 6, rr = i & 63;
      sh[a * SH2 + rr] = sy[rr * 64 + a];
    }
    __syncthreads();
    for (int a0 = 0; a0 < 64; a0 += 16)
      mm_nt_16(sh, SH2, sh, SH2, 64, g_H, 64, a0, 1.0f);
    __syncthreads();
    for (int i = tid; i < 4096; i += 256) {
      int rr = i >> 6, cc = i & 63;
      float h = g_H[i];
      g_HL[i]  = h * (ey[rr] + ey[cc]);
      g_LHL[i] = ey[rr] * h * ey[cc];
    }
    signalflag(4);

  } else if (bid == 203) {
    // ---- Hinv = Sy Sy^T ----
    waitflag(3, 1);
    for (int a0 = 0; a0 < 64; a0 += 16)
      mm_nt_16(g_Sy, 64, g_Sy, 64, 64, g_Hinv, 64, a0, 1.0f);
    signalflag(5);

  } else if (bid < 207) {
    // ---- M_j = S^T lx^j S (j: 204->2, 205->1, 206->0) via sqrt weighting ----
    const int t = bid - 204;            // 0,1,2
    const int jc = t * 64;
    waitflag(2, 1);
    for (int i = tid; i < 4096; i += 256) {
      int a = i >> 6, ii = i & 63;
      float w = (t == 0) ? ex[ii] : ((t == 1) ? sqrtf(ex[ii]) : 1.0f);
      sh[a * SH2 + ii] = g_S[ii * 64 + a] * w;
    }
    __syncthreads();
    for (int a0 = 0; a0 < 64; a0 += 16)
      mm_nt_16(sh, SH2, sh, SH2, 64, g_Mcat + jc, 192, a0, 1.0f);
    signalflag(8 + t);

  } else if (bid < 211) {
    // ---- G = A A^T (16-row slab each) ----
    waitflag(0, 100);
    mm_nt_16(g_AP[0], MDIM, g_AP[0], MDIM, MDIM, g_G, 64, (bid - 207) * 16, 1.0f);
    signalflag(6);

  } else if (bid < 215) {
    // ---- T1 = Py A^T (16-row slab each) ----
    waitflag(0, 100);
    waitflag(1, 100);
    mm_nt_16(g_AP[1], MDIM, g_AP[0], MDIM, MDIM, g_T1, 64, (bid - 211) * 16, 1.0f);
    signalflag(7);

  } else if (bid == 215) {
    // ---- Ginv = inv(G) ----
    waitflag(6, 4);
    gj_inverse_reg(g_G, g_Ginv);
    signalflag(11);

  } else if (bid < 219) {
    // ---- NT slab j: NT[jc+b][k] = sum_u GinvT[jc+b? no: b'][u] * M_j[k][u] ----
    const int t = bid - 216;
    const int jc = t * 64;
    waitflag(8 + t, 1);
    waitflag(11, 1);
    for (int i = tid; i < 4096; i += 256) {
      int b = i >> 6, u = i & 63;
      sh[b * SH2 + u] = g_Ginv[u * 64 + b];   // GinvT
    }
    __syncthreads();
    for (int a0 = 0; a0 < 64; a0 += 16)
      mm_nt_16(sh, SH2, g_Mcat + jc, 192, 64, g_NT + jc * 64, 64, a0, 1.0f);
    signalflag(12);

  } else if (bid < 221) {
    // ---- LP halves: [-Hinv*HL | Hinv*LHL]  (HL, LHL symmetric -> NT ok) ----
    const int t = bid - 219;   // 0: left, 1: right
    waitflag(5, 1);
    waitflag(4, 1);
    const float* Q = t ? g_LHL : g_HL;
    const float scale = t ? 1.0f : -1.0f;
    const int off = t ? 64 : 0;
    for (int a0 = 0; a0 < 64; a0 += 16)
      mm_nt_16(g_Hinv, 64, Q, 64, 64, g_LP + off, 128, a0, scale);
    signalflag(13);

  } else {
    // ---- persistent iteration blocks (4), 16 rows each ----
    const int rb = bid - 221;
    const int rowbase = rb * 16;
    waitflag(7, 4);    // T1
    waitflag(11, 1);   // Ginv
    waitflag(12, 3);   // NT
    waitflag(13, 2);   // LP
    // X0 slab = T1_slab @ Ginv  (NT-form with GinvT staged)
    for (int i = tid; i < 4096; i += 256) {
      int b = i >> 6, u = i & 63;
      sh[b * SH2 + u] = g_Ginv[u * 64 + b];
    }
    __syncthreads();
    mm_nt_16(g_T1 + rowbase * 64, 64, sh, SH2, 64, g_X0 + rowbase * 64, 64, 0, 1.0f);
    __syncthreads();
    const int a  = tid >> 4;            // 0..15 local row
    const int b0 = (tid & 15) << 2;
    float x0v[4], xv[4];
#pragma unroll
    for (int j = 0; j < 4; j++) {
      x0v[j] = g_X0[(rowbase + a) * 64 + b0 + j];
      xv[j] = x0v[j];
    }
    for (int it = 0; it < NITER; it++) {
      float* Vbuf = g_V[it & 1];
      __syncthreads();    // protect sh reuse (VsT of prev iter fully read)
#pragma unroll
      for (int j = 0; j < 4; j++) sh[a * SH2 + b0 + j] = xv[j];
      __syncthreads();
      // V slab rows = Xs @ N  ( = Xs (NT)^T ), 3 column slabs of 64
      mm_nt_16(sh, SH2, g_NT,            64, 64, Vbuf + rowbase * 192 + 0,   192, 0, 1.0f);
      mm_nt_16(sh, SH2, g_NT + 64 * 64,  64, 64, Vbuf + rowbase * 192 + 64,  192, 0, 1.0f);
      mm_nt_16(sh, SH2, g_NT + 128 * 64, 64, 64, Vbuf + rowbase * 192 + 128, 192, 0, 1.0f);
      // inter-block barrier: all 4 blocks' V written
      __threadfence();
      __syncthreads();
      if (tid == 0) {
        atomicAdd(&g_flags[16 + it], 1);
        while (((volatile int*)g_flags)[16 + it] < 4) { }
      }
      __syncthreads();
      // VsT[b][u] : u<64 -> V[u][64+b], u>=64 -> V[u-64][128+b] (ldcg: cross-block)
      for (int i = tid; i < 8192; i += 256) {
        int b = i >> 7, u = i & 127;
        float v = (u < 64) ? __ldcg(&Vbuf[u * 192 + 64 + b])
                           : __ldcg(&Vbuf[(u - 64) * 192 + 128 + b]);
        sh[b * SRV + u] = v;
      }
      __syncthreads();
      float acc[4] = {0.f, 0.f, 0.f, 0.f};
      const float4* LPr = (const float4*)(g_LP + (rowbase + a) * 128);
#pragma unroll 8
      for (int k = 0; k < 32; k++) {
        float4 lp = LPr[k];
#pragma unroll
        for (int jj = 0; jj < 4; jj++) {
          float4 vv = *(const float4*)(sh + (b0 + jj) * SRV + k * 4);
          acc[jj] += lp.x * vv.x + lp.y * vv.y + lp.z * vv.z + lp.w * vv.w;
        }
      }
#pragma unroll
      for (int jj = 0; jj < 4; jj++)
        xv[jj] = x0v[jj] - LMBDA * (Vbuf[(rowbase + a) * 192 + b0 + jj] + acc[jj]);
    }
#pragma unroll
    for (int jj = 0; jj < 4; jj++)
      outp[(rowbase + a) * 64 + b0 + jj] = xv[jj];
  }
}

// ---------------- launch ----------------
extern "C" void kernel_launch(void* const* d_in, const int* in_sizes, int n_in,
                              void* d_out, int out_size) {
  const float* fx = (const float*)d_in[0];   // [1,5000,256]
  const float* fy = (const float*)d_in[1];   // [1,5000,256]
  const float* ex = (const float*)d_in[2];   // [1,64]
  const float* ey = (const float*)d_in[3];   // [1,64]
  const float* tx = (const float*)d_in[4];   // [1,64,5000]
  const float* ty = (const float*)d_in[5];   // [1,64,5000]
  const float* sx = (const float*)d_in[6];   // [1,64,64]
  const float* sy = (const float*)d_in[7];   // [1,64,64]
  float* out = (float*)d_out;                // [1,64,64] float32

  reset_kernel<<<33, 256>>>();
  mega_kernel<<<225, 256>>>(fx, fy, ex, ey, tx, ty, sx, sy, out);
}

// round 7
// speedup vs baseline: 1.4363x; 1.4363x over previous
#include <cuda_runtime.h>
#include <math.h>

#define KD 64
#define MDIM 256
#define VDIM 5000
#define LMBDA 0.001f
#define NITER 6
#define VCHUNK 200
#define SH2 68     // staging stride (floats)

// ---------------- device scratch ----------------
__device__ float g_AP[2][KD * MDIM];     // [0]=A=tx@fx, [1]=Py=ty@fy
__device__ float g_S[KD * KD];           // inv(sx)
__device__ float g_Sy[KD * KD];          // inv(sy)
__device__ float g_H[KD * KD];           // sy^T sy
__device__ float g_G[KD * KD];           // A A^T
__device__ float g_T1[KD * KD];          // Py A^T
__device__ float g_Mcat[KD * 192];       // [M2 | M1 | M0]
__device__ float g_NT[192 * KD];         // NT[c][k] = Ncat[k][c], Ncat=[N2|N1|N0]
__device__ float g_Hinv[KD * KD];
__device__ float g_Ginv[KD * KD];
__device__ float g_HL[KD * KD];          // H ly + ly H   (symmetric)
__device__ float g_LHL[KD * KD];         // ly H ly       (symmetric)
__device__ float g_LP[KD * 128];         // [-Hinv HL | Hinv LHL]
__device__ float g_X0[KD * KD];
__device__ float g_Vd[2][KD * 128];      // double-buffered V cols 64..191

// ---------------- sync ----------------
__device__ __forceinline__ void cluster_sync_fence() {
  __threadfence();
  asm volatile("barrier.cluster.arrive.aligned;" ::: "memory");
  asm volatile("barrier.cluster.wait.aligned;" ::: "memory");
}

// ---------------- helpers ----------------

// C[a0..a0+15][0..63] = scale * sum_k P[a][k]*Q[b][k]; strides multiples of 4.
// Requires blockDim.x == 256.
__device__ __forceinline__ void mm_nt_16(
    const float* __restrict__ P, int ldp,
    const float* __restrict__ Q, int ldq,
    int Klen, float* __restrict__ C, int ldc, int a0, float scale) {
  const int tid = threadIdx.x;
  const int a = a0 + (tid >> 4);
  const int b0 = (tid & 15) << 2;
  float acc0 = 0.f, acc1 = 0.f, acc2 = 0.f, acc3 = 0.f;
  const float4* Pr = (const float4*)(P + a * ldp);
  const float4* Q0 = (const float4*)(Q + (b0 + 0) * ldq);
  const float4* Q1 = (const float4*)(Q + (b0 + 1) * ldq);
  const float4* Q2 = (const float4*)(Q + (b0 + 2) * ldq);
  const float4* Q3 = (const float4*)(Q + (b0 + 3) * ldq);
  const int k4 = Klen >> 2;
  for (int k = 0; k < k4; k++) {
    float4 av = Pr[k];
    float4 bv;
    bv = Q0[k]; acc0 += av.x * bv.x + av.y * bv.y + av.z * bv.z + av.w * bv.w;
    bv = Q1[k]; acc1 += av.x * bv.x + av.y * bv.y + av.z * bv.z + av.w * bv.w;
    bv = Q2[k]; acc2 += av.x * bv.x + av.y * bv.y + av.z * bv.z + av.w * bv.w;
    bv = Q3[k]; acc3 += av.x * bv.x + av.y * bv.y + av.z * bv.z + av.w * bv.w;
  }
  float* Cr = C + a * ldc + b0;
  Cr[0] = acc0 * scale; Cr[1] = acc1 * scale;
  Cr[2] = acc2 * scale; Cr[3] = acc3 * scale;
}

// Register-resident pivot-free Gauss-Jordan inverse of a 64x64 (inputs SPD or
// near-identity). 256 threads; thread owns column c=tid&63, rows r0+4q.
// Pipelined: next pivot's row/col published in same phase -> 1 barrier/pivot.
__device__ void gj_inverse_reg(const float* __restrict__ in,
                               float* __restrict__ out) {
  __shared__ float prow[2][64];
  __shared__ float pcol[2][64];
  const int tid = threadIdx.x;
  const int r0 = tid >> 6;        // 0..3
  const int c  = tid & 63;
  float v[16];
#pragma unroll
  for (int q = 0; q < 16; q++) v[q] = in[(r0 + 4 * q) * 64 + c];
  if (c == 0) {
#pragma unroll
    for (int q = 0; q < 16; q++) pcol[0][r0 + 4 * q] = v[q];
  }
  if (r0 == 0) prow[0][c] = v[0];
  __syncthreads();
  for (int p = 0; p < 64; p++) {
    const int cur = p & 1, nxt = cur ^ 1;
    const float dinv = 1.0f / prow[cur][p];
    const float prc = prow[cur][c] * dinv;
    if (c == p) {
#pragma unroll
      for (int q = 0; q < 16; q++) {
        int r = r0 + 4 * q;
        v[q] = (r == p) ? dinv : -v[q] * dinv;
      }
    } else {
#pragma unroll
      for (int q = 0; q < 16; q++) {
        int r = r0 + 4 * q;
        v[q] = (r == p) ? prc : fmaf(-pcol[cur][r], prc, v[q]);
      }
    }
    if (p < 63) {
      const int pn = p + 1;
      if (c == pn) {
#pragma unroll
        for (int q = 0; q < 16; q++) pcol[nxt][r0 + 4 * q] = v[q];
      }
      if (r0 == (pn & 3)) prow[nxt][c] = v[pn >> 2];
    }
    __syncthreads();
  }
#pragma unroll
  for (int q = 0; q < 16; q++) out[(r0 + 4 * q) * 64 + c] = v[q];
}

// ---------------- kernel 1: prep (4-CTA cluster) ----------------
__global__ void __cluster_dims__(4, 1, 1) __launch_bounds__(256, 1)
prep_kernel(const float* __restrict__ sx, const float* __restrict__ sy,
            const float* __restrict__ ex, const float* __restrict__ ey) {
  __shared__ __align__(16) float sh[64 * SH2];
  const int rk = blockIdx.x;
  const int tid = threadIdx.x;

  if (rk == 0) {
    gj_inverse_reg(sx, g_S);
  } else if (rk == 1) {
    gj_inverse_reg(sy, g_Sy);
  } else if (rk == 2) {
    // H = sy^T sy; HL = H.*(ey_r+ey_c); LHL = ey_r.*H.*ey_c
    for (int i = tid; i < 4096; i += 256) {
      int a = i >> 6, rr = i & 63;
      sh[a * SH2 + rr] = sy[rr * 64 + a];
    }
    __syncthreads();
    for (int a0 = 0; a0 < 64; a0 += 16)
      mm_nt_16(sh, SH2, sh, SH2, 64, g_H, 64, a0, 1.0f);
    __syncthreads();
    for (int i = tid; i < 4096; i += 256) {
      int rr = i >> 6, cc = i & 63;
      float h = g_H[i];
      g_HL[i]  = h * (ey[rr] + ey[cc]);
      g_LHL[i] = ey[rr] * h * ey[cc];
    }
  } else {
    // zero split-K accumulators
    float4 z = make_float4(0.f, 0.f, 0.f, 0.f);
    float4* p = (float4*)g_AP;
    for (int i = tid; i < (2 * KD * MDIM) / 4; i += 256) p[i] = z;
  }
  cluster_sync_fence();
  if (rk < 3) {
    // M_j = S^T lx^j S via sqrt weighting (rk: 0->M2, 1->M1, 2->M0)
    const int jc = rk * 64;
    for (int i = tid; i < 4096; i += 256) {
      int a = i >> 6, ii = i & 63;
      float w = (rk == 0) ? ex[ii] : ((rk == 1) ? sqrtf(ex[ii]) : 1.0f);
      sh[a * SH2 + ii] = g_S[ii * 64 + a] * w;
    }
    __syncthreads();
    for (int a0 = 0; a0 < 64; a0 += 16)
      mm_nt_16(sh, SH2, sh, SH2, 64, g_Mcat + jc, 192, a0, 1.0f);
  } else {
    // Hinv = Sy Sy^T
    for (int a0 = 0; a0 < 64; a0 += 16)
      mm_nt_16(g_Sy, 64, g_Sy, 64, 64, g_Hinv, 64, a0, 1.0f);
  }
}

// ---------------- kernel 2: big gemm (split-K, double-buffered) ----------------
__global__ void __launch_bounds__(256)
gemm_kernel(const float* __restrict__ fx, const float* __restrict__ fy,
            const float* __restrict__ tx, const float* __restrict__ ty) {
  __shared__ __align__(16) float Ws[8 * 64];
  __shared__ __align__(16) float Fs[8 * 64];
  const int bid = blockIdx.x;
  const int mat = bid / 100;
  const int r   = bid % 100;
  const int mt  = r & 3;
  const int vs  = r >> 2;
  const float* __restrict__ F  = mat ? fy : fx;   // [VDIM][MDIM]
  const float* __restrict__ Wm = mat ? ty : tx;   // [KD][VDIM]
  float* out = g_AP[mat];
  const int m0 = mt * 64;
  const int v0 = vs * VCHUNK;
  const int tid = threadIdx.x;
  // element A: idx=tid; element B: idx=tid+256
  const int kkA = tid & 7,  rowA = tid >> 3;
  const int kk2A = tid >> 6, colA = tid & 63;
  const int idxB = tid + 256;
  const int kkB = idxB & 7,  rowB = idxB >> 3;
  const int kk2B = idxB >> 6, colB = idxB & 63;
  const float* WA = Wm + rowA * VDIM + kkA;
  const float* WB = Wm + rowB * VDIM + kkB;
  const float* FA = F + kk2A * MDIM + m0 + colA;
  const float* FB = F + kk2B * MDIM + m0 + colB;
  const int tr = (tid >> 4) << 2;
  const int tc = (tid & 15) << 2;
  float acc[4][4];
#pragma unroll
  for (int i = 0; i < 4; i++)
#pragma unroll
    for (int j = 0; j < 4; j++) acc[i][j] = 0.f;

  float w0 = WA[v0], w1 = WB[v0];
  float f0 = FA[v0 * MDIM], f1 = FB[v0 * MDIM];
  for (int vv = v0; vv < v0 + VCHUNK; vv += 8) {
    Ws[kkA * 64 + rowA] = w0;
    Ws[kkB * 64 + rowB] = w1;
    Fs[kk2A * 64 + colA] = f0;
    Fs[kk2B * 64 + colB] = f1;
    __syncthreads();
    const int nv = vv + 8;
    if (nv < v0 + VCHUNK) {
      w0 = WA[nv]; w1 = WB[nv];
      f0 = FA[nv * MDIM]; f1 = FB[nv * MDIM];
    }
#pragma unroll
    for (int kk = 0; kk < 8; kk++) {
      float4 av = *(const float4*)&Ws[kk * 64 + tr];
      float4 bv = *(const float4*)&Fs[kk * 64 + tc];
      acc[0][0] += av.x * bv.x; acc[0][1] += av.x * bv.y; acc[0][2] += av.x * bv.z; acc[0][3] += av.x * bv.w;
      acc[1][0] += av.y * bv.x; acc[1][1] += av.y * bv.y; acc[1][2] += av.y * bv.z; acc[1][3] += av.y * bv.w;
      acc[2][0] += av.z * bv.x; acc[2][1] += av.z * bv.y; acc[2][2] += av.z * bv.z; acc[2][3] += av.z * bv.w;
      acc[3][0] += av.w * bv.x; acc[3][1] += av.w * bv.y; acc[3][2] += av.w * bv.z; acc[3][3] += av.w * bv.w;
    }
    __syncthreads();
  }
#pragma unroll
  for (int i = 0; i < 4; i++)
#pragma unroll
    for (int j = 0; j < 4; j++)
      atomicAdd(&out[(tr + i) * MDIM + m0 + tc + j], acc[i][j]);
}

// ---------------- kernel 3: solve (8-CTA cluster) ----------------
__global__ void __cluster_dims__(8, 1, 1) __launch_bounds__(256, 1)
solve_kernel(float* __restrict__ outp) {
  // 47104 B multi-use shared
  __shared__ __align__(16) float sh[11776];
  const int rk = blockIdx.x;       // cluster rank 0..7
  const int tid = threadIdx.x;

  // ---- Phase A: G (ranks 0-3) / T1 (ranks 4-7), 16-row slabs ----
  if (rk < 4) {
    mm_nt_16(g_AP[0], MDIM, g_AP[0], MDIM, MDIM, g_G, 64, rk * 16, 1.0f);
  } else {
    mm_nt_16(g_AP[1], MDIM, g_AP[0], MDIM, MDIM, g_T1, 64, (rk - 4) * 16, 1.0f);
  }
  cluster_sync_fence();

  // ---- Phase B: Ginv = inv(G) on rank 0 ----
  if (rk == 0) gj_inverse_reg(g_G, g_Ginv);
  cluster_sync_fence();

  // ---- Phase C: NT slabs / LP halves / X0 ----
  if (rk < 3) {
    const int jc = rk * 64;
    for (int i = tid; i < 4096; i += 256) {
      int b = i >> 6, u = i & 63;
      sh[b * SH2 + u] = g_Ginv[u * 64 + b];     // GinvT
    }
    __syncthreads();
    // NT[jc+c'][k] = sum_u GinvT[c'][u] * M_j[k][u]
    for (int a0 = 0; a0 < 64; a0 += 16)
      mm_nt_16(sh, SH2, g_Mcat + jc, 192, 64, g_NT + jc * 64, 64, a0, 1.0f);
  } else if (rk < 5) {
    const int t = rk - 3;          // 0: left (-Hinv HL), 1: right (Hinv LHL)
    const float* Q = t ? g_LHL : g_HL;   // symmetric -> NT form ok
    const float scale = t ? 1.0f : -1.0f;
    const int off = t ? 64 : 0;
    for (int a0 = 0; a0 < 64; a0 += 16)
      mm_nt_16(g_Hinv, 64, Q, 64, 64, g_LP + off, 128, a0, scale);
  } else if (rk < 7) {
    // X0 = T1 @ Ginv, rows (rk-5)*32 .. +31
    for (int i = tid; i < 4096; i += 256) {
      int b = i >> 6, u = i & 63;
      sh[b * SH2 + u] = g_Ginv[u * 64 + b];     // GinvT
    }
    __syncthreads();
    const int base = (rk - 5) * 32;
    mm_nt_16(g_T1, 64, sh, SH2, 64, g_X0, 64, base, 1.0f);
    mm_nt_16(g_T1, 64, sh, SH2, 64, g_X0, 64, base + 16, 1.0f);
  }
  cluster_sync_fence();

  // ---- Phase D: Richardson iterations; CTA owns 8 rows ----
  const int rowbase = rk * 8;
  float* Vcs = sh;                 // [64][128] = 8192 floats
  float* LPs = sh + 8192;          // [8][128]  = 1024 floats
  float* Xs  = sh + 8192 + 1024;   // [8][SH2]  = 544 floats
  for (int i = tid; i < 1024; i += 256)
    LPs[i] = g_LP[(rowbase + (i >> 7)) * 128 + (i & 127)];
  for (int i = tid; i < 512; i += 256) {
    int a = i >> 6, b = i & 63;
    Xs[a * SH2 + b] = g_X0[(rowbase + a) * 64 + b];
  }
  const int a    = tid >> 5;       // 0..7 local row
  const int lane = tid & 31;
  float x0v0 = g_X0[(rowbase + a) * 64 + lane];
  float x0v1 = g_X0[(rowbase + a) * 64 + lane + 32];
  __syncthreads();

  for (int it = 0; it < NITER; it++) {
    float* Vbuf = g_Vd[it & 1];
    // V[a][c] = sum_k Xs[a][k] * NT[c][k], cols c = lane + 32j, j=0..5
    float vacc[6] = {0.f, 0.f, 0.f, 0.f, 0.f, 0.f};
    const float4* xr = (const float4*)(Xs + a * SH2);
    const float4* nt0 = (const float4*)(g_NT + (lane +   0) * 64);
    const float4* nt1 = (const float4*)(g_NT + (lane +  32) * 64);
    const float4* nt2 = (const float4*)(g_NT + (lane +  64) * 64);
    const float4* nt3 = (const float4*)(g_NT + (lane +  96) * 64);
    const float4* nt4 = (const float4*)(g_NT + (lane + 128) * 64);
    const float4* nt5 = (const float4*)(g_NT + (lane + 160) * 64);
#pragma unroll
    for (int k4 = 0; k4 < 16; k4++) {
      float4 xv4 = xr[k4];
      float4 n;
      n = nt0[k4]; vacc[0] += xv4.x*n.x + xv4.y*n.y + xv4.z*n.z + xv4.w*n.w;
      n = nt1[k4]; vacc[1] += xv4.x*n.x + xv4.y*n.y + xv4.z*n.z + xv4.w*n.w;
      n = nt2[k4]; vacc[2] += xv4.x*n.x + xv4.y*n.y + xv4.z*n.z + xv4.w*n.w;
      n = nt3[k4]; vacc[3] += xv4.x*n.x + xv4.y*n.y + xv4.z*n.z + xv4.w*n.w;
      n = nt4[k4]; vacc[4] += xv4.x*n.x + xv4.y*n.y + xv4.z*n.z + xv4.w*n.w;
      n = nt5[k4]; vacc[5] += xv4.x*n.x + xv4.y*n.y + xv4.z*n.z + xv4.w*n.w;
    }
    // write V cols 64..191 (j=2..5) to global for cluster exchange
    Vbuf[(rowbase + a) * 128 + lane +  0] = vacc[2];
    Vbuf[(rowbase + a) * 128 + lane + 32] = vacc[3];
    Vbuf[(rowbase + a) * 128 + lane + 64] = vacc[4];
    Vbuf[(rowbase + a) * 128 + lane + 96] = vacc[5];
    cluster_sync_fence();
    // stage full Vc (64 rows x 128) into shared
    for (int i = tid; i < 8192; i += 256) Vcs[i] = Vbuf[i];
    __syncthreads();
    // corr[a][b] = sum_{u<64} LP[a][u]*Vcs[u][b] + LP[a][64+u]*Vcs[u][64+b]
    float c0 = 0.f, c1 = 0.f;
#pragma unroll 8
    for (int u = 0; u < 64; u++) {
      float lpA = LPs[a * 128 + u];
      float lpB = LPs[a * 128 + 64 + u];
      const float* vr = Vcs + u * 128;
      c0 += lpA * vr[lane]      + lpB * vr[64 + lane];
      c1 += lpA * vr[lane + 32] + lpB * vr[96 + lane];
    }
    float xn0 = x0v0 - LMBDA * (vacc[0] + c0);
    float xn1 = x0v1 - LMBDA * (vacc[1] + c1);
    if (it == NITER - 1) {
      outp[(rowbase + a) * 64 + lane]      = xn0;
      outp[(rowbase + a) * 64 + lane + 32] = xn1;
    } else {
      __syncthreads();           // everyone done reading Xs/Vcs
      Xs[a * SH2 + lane]      = xn0;
      Xs[a * SH2 + lane + 32] = xn1;
      __syncthreads();
    }
  }
}

// ---------------- launch ----------------
extern "C" void kernel_launch(void* const* d_in, const int* in_sizes, int n_in,
                              void* d_out, int out_size) {
  const float* fx = (const float*)d_in[0];   // [1,5000,256]
  const float* fy = (const float*)d_in[1];   // [1,5000,256]
  const float* ex = (const float*)d_in[2];   // [1,64]
  const float* ey = (const float*)d_in[3];   // [1,64]
  const float* tx = (const float*)d_in[4];   // [1,64,5000]
  const float* ty = (const float*)d_in[5];   // [1,64,5000]
  const float* sx = (const float*)d_in[6];   // [1,64,64]
  const float* sy = (const float*)d_in[7];   // [1,64,64]
  float* out = (float*)d_out;                // [1,64,64] float32

  prep_kernel<<<4, 256>>>(sx, sy, ex, ey);
  gemm_kernel<<<200, 256>>>(fx, fy, tx, ty);
  solve_kernel<<<8, 256>>>(out);
}

// round 13
// speedup vs baseline: 1.6607x; 1.1562x over previous
#include <cuda_runtime.h>
#include <math.h>

#define KD 64
#define MDIM 256
#define VDIM 5000
#define LMBDA 0.001f
#define NITER 6
#define VCHUNK 200
#define SH2 68     // staging stride (floats)

// ---------------- device scratch ----------------
__device__ float g_AP[2][KD * MDIM];     // [0]=A=tx@fx, [1]=Py=ty@fy
__device__ float g_S[KD * KD];           // inv(sx)
__device__ float g_Sy[KD * KD];          // inv(sy)
__device__ float g_H[KD * KD];           // sy^T sy
__device__ float g_G[KD * KD];           // A A^T
__device__ float g_T1[KD * KD];          // Py A^T
__device__ float g_Mcat[KD * 192];       // [M2 | M1 | M0]
__device__ float g_NT[192 * KD];         // NT[c][k] = Ncat[k][c], Ncat=[N2|N1|N0]
__device__ float g_Hinv[KD * KD];
__device__ float g_Ginv[KD * KD];
__device__ float g_HL[KD * KD];          // H ly + ly H   (symmetric)
__device__ float g_LHL[KD * KD];         // ly H ly       (symmetric)
__device__ float g_LP[KD * 128];         // [-Hinv HL | Hinv LHL]
__device__ float g_X0[KD * KD];
__device__ float g_Vd[2][KD * 128];      // double-buffered V cols 64..191

// ---------------- sync ----------------
__device__ __forceinline__ void cluster_sync_fence() {
  __threadfence();
  asm volatile("barrier.cluster.arrive.aligned;" ::: "memory");
  asm volatile("barrier.cluster.wait.aligned;" ::: "memory");
}

// ---------------- helpers ----------------

// C[a0..a0+15][0..63] = scale * sum_k P[a][k]*Q[b][k]; strides multiples of 4.
// Requires blockDim.x == 256.
__device__ __forceinline__ void mm_nt_16(
    const float* __restrict__ P, int ldp,
    const float* __restrict__ Q, int ldq,
    int Klen, float* __restrict__ C, int ldc, int a0, float scale) {
  const int tid = threadIdx.x;
  const int a = a0 + (tid >> 4);
  const int b0 = (tid & 15) << 2;
  float acc0 = 0.f, acc1 = 0.f, acc2 = 0.f, acc3 = 0.f;
  const float4* Pr = (const float4*)(P + a * ldp);
  const float4* Q0 = (const float4*)(Q + (b0 + 0) * ldq);
  const float4* Q1 = (const float4*)(Q + (b0 + 1) * ldq);
  const float4* Q2 = (const float4*)(Q + (b0 + 2) * ldq);
  const float4* Q3 = (const float4*)(Q + (b0 + 3) * ldq);
  const int k4 = Klen >> 2;
  for (int k = 0; k < k4; k++) {
    float4 av = Pr[k];
    float4 bv;
    bv = Q0[k]; acc0 += av.x * bv.x + av.y * bv.y + av.z * bv.z + av.w * bv.w;
    bv = Q1[k]; acc1 += av.x * bv.x + av.y * bv.y + av.z * bv.z + av.w * bv.w;
    bv = Q2[k]; acc2 += av.x * bv.x + av.y * bv.y + av.z * bv.z + av.w * bv.w;
    bv = Q3[k]; acc3 += av.x * bv.x + av.y * bv.y + av.z * bv.z + av.w * bv.w;
  }
  float* Cr = C + a * ldc + b0;
  Cr[0] = acc0 * scale; Cr[1] = acc1 * scale;
  Cr[2] = acc2 * scale; Cr[3] = acc3 * scale;
}

// Register-resident pivot-free Gauss-Jordan inverse of a 64x64.
// 256 threads: thread owns CONTIGUOUS rows [16*r0, 16*r0+16) at column c=tid&63.
// Pivot loop unrolled x16 so every register-array index is compile-time static.
// pcol reads are 4x LDS.128. Unified update: v = fma(-pc, w, base), with
// w = cp ? dinv : prc and base = cp ? 0 : v selected per thread, plus one
// static fixup for the q==j (pivot-row) element. One barrier per pivot.
__device__ void gj_inverse_reg(const float* __restrict__ in,
                               float* __restrict__ out) {
  __shared__ __align__(16) float prow[2][64];
  __shared__ __align__(16) float pcol[2][64];
  const int tid = threadIdx.x;
  const int r0 = tid >> 6;        // 0..3 -> rows 16*r0 .. 16*r0+15
  const int c  = tid & 63;
  float v[16];
#pragma unroll
  for (int q = 0; q < 16; q++) v[q] = in[(r0 * 16 + q) * 64 + c];
  // publish pivot 0 (pre-update values)
  if (c == 0) {
#pragma unroll
    for (int q = 0; q < 16; q++) pcol[0][r0 * 16 + q] = v[q];
  }
  if (r0 == 0) prow[0][c] = v[0];
  __syncthreads();
  for (int po = 0; po < 4; po++) {
#pragma unroll
    for (int j = 0; j < 16; j++) {
      const int p = po * 16 + j;
      const int cur = p & 1, nxt = cur ^ 1;
      const float piv = prow[cur][p];
      const float dinv = 1.0f / piv;
      const float prc = prow[cur][c] * dinv;
      const bool cp = (c == p);
      const bool rown = (r0 == po);
      const float w = cp ? dinv : prc;
      float pc[16];
      {
        const float4* pcb = (const float4*)&pcol[cur][r0 * 16];
        float4 t0 = pcb[0], t1 = pcb[1], t2 = pcb[2], t3 = pcb[3];
        pc[0]=t0.x; pc[1]=t0.y; pc[2]=t0.z; pc[3]=t0.w;
        pc[4]=t1.x; pc[5]=t1.y; pc[6]=t1.z; pc[7]=t1.w;
        pc[8]=t2.x; pc[9]=t2.y; pc[10]=t2.z; pc[11]=t2.w;
        pc[12]=t3.x; pc[13]=t3.y; pc[14]=t3.z; pc[15]=t3.w;
      }
#pragma unroll
      for (int q = 0; q < 16; q++) {
        float base = cp ? 0.0f : v[q];
        v[q] = fmaf(-pc[q], w, base);
      }
      // fixup the pivot-row element (static index j)
      if (rown) v[j] = cp ? dinv : prc;
      // publish next pivot (post-update values, static indices)
      if (p < 63) {
        const int pn = p + 1;
        if (c == pn) {
#pragma unroll
          for (int q = 0; q < 16; q++) pcol[nxt][r0 * 16 + q] = v[q];
        }
        if (r0 == (pn >> 4)) prow[nxt][c] = v[(j + 1) & 15];
      }
      __syncthreads();
    }
  }
#pragma unroll
  for (int q = 0; q < 16; q++) out[(r0 * 16 + q) * 64 + c] = v[q];
}

// ---------------- kernel 0: zero split-K accumulators ----------------
__global__ void zero_kernel() {
  int i = blockIdx.x * 256 + threadIdx.x;
  ((float4*)g_AP)[i] = make_float4(0.f, 0.f, 0.f, 0.f);
}

// ---------------- kernel 1: gemm + independent prep blocks ----------------
// bid<200: split-K gemm. bid==200: S=inv(sx). 201: Sy=inv(sy). 202: H/HL/LHL.
__global__ void __launch_bounds__(256, 2)
work_kernel(const float* __restrict__ fx, const float* __restrict__ fy,
            const float* __restrict__ tx, const float* __restrict__ ty,
            const float* __restrict__ sx, const float* __restrict__ sy,
            const float* __restrict__ ey) {
  __shared__ __align__(16) float shw[64 * SH2];   // 17KB multi-use
  const int bid = blockIdx.x;
  const int tid = threadIdx.x;

  if (bid < 200) {
    float* Ws = shw;          // [8][64]
    float* Fs = shw + 512;    // [8][64]
    const int mat = bid / 100;
    const int r   = bid % 100;
    const int mt  = r & 3;
    const int vs  = r >> 2;
    const float* __restrict__ F  = mat ? fy : fx;   // [VDIM][MDIM]
    const float* __restrict__ Wm = mat ? ty : tx;   // [KD][VDIM]
    float* out = g_AP[mat];
    const int m0 = mt * 64;
    const int v0 = vs * VCHUNK;
    const int kkA = tid & 7,  rowA = tid >> 3;
    const int kk2A = tid >> 6, colA = tid & 63;
    const int idxB = tid + 256;
    const int kkB = idxB & 7,  rowB = idxB >> 3;
    const int kk2B = idxB >> 6, colB = idxB & 63;
    const float* WA = Wm + rowA * VDIM + kkA;
    const float* WB = Wm + rowB * VDIM + kkB;
    const float* FA = F + kk2A * MDIM + m0 + colA;
    const float* FB = F + kk2B * MDIM + m0 + colB;
    const int tr = (tid >> 4) << 2;
    const int tc = (tid & 15) << 2;
    float acc[4][4];
#pragma unroll
    for (int i = 0; i < 4; i++)
#pragma unroll
      for (int j = 0; j < 4; j++) acc[i][j] = 0.f;

    float w0 = WA[v0], w1 = WB[v0];
    float f0 = FA[v0 * MDIM], f1 = FB[v0 * MDIM];
    for (int vv = v0; vv < v0 + VCHUNK; vv += 8) {
      Ws[kkA * 64 + rowA] = w0;
      Ws[kkB * 64 + rowB] = w1;
      Fs[kk2A * 64 + colA] = f0;
      Fs[kk2B * 64 + colB] = f1;
      __syncthreads();
      const int nv = vv + 8;
      if (nv < v0 + VCHUNK) {
        w0 = WA[nv]; w1 = WB[nv];
        f0 = FA[nv * MDIM]; f1 = FB[nv * MDIM];
      }
#pragma unroll
      for (int kk = 0; kk < 8; kk++) {
        float4 av = *(const float4*)&Ws[kk * 64 + tr];
        float4 bv = *(const float4*)&Fs[kk * 64 + tc];
        acc[0][0] += av.x * bv.x; acc[0][1] += av.x * bv.y; acc[0][2] += av.x * bv.z; acc[0][3] += av.x * bv.w;
        acc[1][0] += av.y * bv.x; acc[1][1] += av.y * bv.y; acc[1][2] += av.y * bv.z; acc[1][3] += av.y * bv.w;
        acc[2][0] += av.z * bv.x; acc[2][1] += av.z * bv.y; acc[2][2] += av.z * bv.z; acc[2][3] += av.z * bv.w;
        acc[3][0] += av.w * bv.x; acc[3][1] += av.w * bv.y; acc[3][2] += av.w * bv.z; acc[3][3] += av.w * bv.w;
      }
      __syncthreads();
    }
#pragma unroll
    for (int i = 0; i < 4; i++)
#pragma unroll
      for (int j = 0; j < 4; j++)
        atomicAdd(&out[(tr + i) * MDIM + m0 + tc + j], acc[i][j]);

  } else if (bid == 200) {
    gj_inverse_reg(sx, g_S);
  } else if (bid == 201) {
    gj_inverse_reg(sy, g_Sy);
  } else {
    // H = sy^T sy; HL = H.*(ey_r+ey_c); LHL = ey_r.*H.*ey_c
    for (int i = tid; i < 4096; i += 256) {
      int a = i >> 6, rr = i & 63;
      shw[a * SH2 + rr] = sy[rr * 64 + a];
    }
    __syncthreads();
    for (int a0 = 0; a0 < 64; a0 += 16)
      mm_nt_16(shw, SH2, shw, SH2, 64, g_H, 64, a0, 1.0f);
    __syncthreads();
    for (int i = tid; i < 4096; i += 256) {
      int rr = i >> 6, cc = i & 63;
      float h = g_H[i];
      g_HL[i]  = h * (ey[rr] + ey[cc]);
      g_LHL[i] = ey[rr] * h * ey[cc];
    }
  }
}

// ---------------- kernel 2: solve (8-CTA cluster) ----------------
__global__ void __cluster_dims__(8, 1, 1) __launch_bounds__(256, 1)
solve_kernel(const float* __restrict__ ex, float* __restrict__ outp) {
  __shared__ __align__(16) float sh[11776];   // 47KB multi-use
  const int rk = blockIdx.x;       // cluster rank 0..7
  const int tid = threadIdx.x;

  // ---- Phase A: G / T1 / M2 / M1 / M0 / Hinv ----
  if (rk < 2) {
    const int base = rk * 32;
    mm_nt_16(g_AP[0], MDIM, g_AP[0], MDIM, MDIM, g_G, 64, base, 1.0f);
    mm_nt_16(g_AP[0], MDIM, g_AP[0], MDIM, MDIM, g_G, 64, base + 16, 1.0f);
  } else if (rk < 4) {
    const int base = (rk - 2) * 32;
    mm_nt_16(g_AP[1], MDIM, g_AP[0], MDIM, MDIM, g_T1, 64, base, 1.0f);
    mm_nt_16(g_AP[1], MDIM, g_AP[0], MDIM, MDIM, g_T1, 64, base + 16, 1.0f);
  } else if (rk < 7) {
    // M_j = S^T lx^j S via sqrt weighting (rk: 4->M2, 5->M1, 6->M0)
    const int t = rk - 4;
    const int jc = t * 64;
    for (int i = tid; i < 4096; i += 256) {
      int a = i >> 6, ii = i & 63;
      float w = (t == 0) ? ex[ii] : ((t == 1) ? sqrtf(ex[ii]) : 1.0f);
      sh[a * SH2 + ii] = g_S[ii * 64 + a] * w;
    }
    __syncthreads();
    for (int a0 = 0; a0 < 64; a0 += 16)
      mm_nt_16(sh, SH2, sh, SH2, 64, g_Mcat + jc, 192, a0, 1.0f);
  } else {
    // Hinv = Sy Sy^T
    for (int a0 = 0; a0 < 64; a0 += 16)
      mm_nt_16(g_Sy, 64, g_Sy, 64, 64, g_Hinv, 64, a0, 1.0f);
  }
  cluster_sync_fence();

  // ---- Phase B: Ginv = inv(G) on rank 0 ----
  if (rk == 0) gj_inverse_reg(g_G, g_Ginv);
  cluster_sync_fence();

  // ---- Phase C: NT slabs / LP halves / X0 ----
  if (rk < 3) {
    const int jc = rk * 64;
    for (int i = tid; i < 4096; i += 256) {
      int b = i >> 6, u = i & 63;
      sh[b * SH2 + u] = g_Ginv[u * 64 + b];     // GinvT
    }
    __syncthreads();
    for (int a0 = 0; a0 < 64; a0 += 16)
      mm_nt_16(sh, SH2, g_Mcat + jc, 192, 64, g_NT + jc * 64, 64, a0, 1.0f);
  } else if (rk < 5) {
    const int t = rk - 3;          // 0: left (-Hinv HL), 1: right (Hinv LHL)
    const float* Q = t ? g_LHL : g_HL;   // symmetric -> NT form ok
    const float scale = t ? 1.0f : -1.0f;
    const int off = t ? 64 : 0;
    for (int a0 = 0; a0 < 64; a0 += 16)
      mm_nt_16(g_Hinv, 64, Q, 64, 64, g_LP + off, 128, a0, scale);
  } else if (rk < 7) {
    // X0 = T1 @ Ginv, rows (rk-5)*32 .. +31
    for (int i = tid; i < 4096; i += 256) {
      int b = i >> 6, u = i & 63;
      sh[b * SH2 + u] = g_Ginv[u * 64 + b];     // GinvT
    }
    __syncthreads();
    const int base = (rk - 5) * 32;
    mm_nt_16(g_T1, 64, sh, SH2, 64, g_X0, 64, base, 1.0f);
    mm_nt_16(g_T1, 64, sh, SH2, 64, g_X0, 64, base + 16, 1.0f);
  }
  cluster_sync_fence();

  // ---- Phase D: Richardson iterations; CTA owns 8 rows ----
  const int rowbase = rk * 8;
  float* Vcs = sh;                 // [64][128] = 8192 floats
  float* LPs = sh + 8192;          // [8][128]  = 1024 floats
  float* Xs  = sh + 8192 + 1024;   // [8][SH2]  = 544 floats
  for (int i = tid; i < 1024; i += 256)
    LPs[i] = g_LP[(rowbase + (i >> 7)) * 128 + (i & 127)];
  for (int i = tid; i < 512; i += 256) {
    int a = i >> 6, b = i & 63;
    Xs[a * SH2 + b] = g_X0[(rowbase + a) * 64 + b];
  }
  const int a    = tid >> 5;       // 0..7 local row
  const int lane = tid & 31;
  float x0v0 = g_X0[(rowbase + a) * 64 + lane];
  float x0v1 = g_X0[(rowbase + a) * 64 + lane + 32];
  __syncthreads();

  for (int it = 0; it < NITER; it++) {
    float* Vbuf = g_Vd[it & 1];
    // V[a][c] = sum_k Xs[a][k] * NT[c][k], cols c = lane + 32j, j=0..5
    float vacc[6] = {0.f, 0.f, 0.f, 0.f, 0.f, 0.f};
    const float4* xr = (const float4*)(Xs + a * SH2);
    const float4* nt0 = (const float4*)(g_NT + (lane +   0) * 64);
    const float4* nt1 = (const float4*)(g_NT + (lane +  32) * 64);
    const float4* nt2 = (const float4*)(g_NT + (lane +  64) * 64);
    const float4* nt3 = (const float4*)(g_NT + (lane +  96) * 64);
    const float4* nt4 = (const float4*)(g_NT + (lane + 128) * 64);
    const float4* nt5 = (const float4*)(g_NT + (lane + 160) * 64);
#pragma unroll
    for (int k4 = 0; k4 < 16; k4++) {
      float4 xv4 = xr[k4];
      float4 n;
      n = nt0[k4]; vacc[0] += xv4.x*n.x + xv4.y*n.y + xv4.z*n.z + xv4.w*n.w;
      n = nt1[k4]; vacc[1] += xv4.x*n.x + xv4.y*n.y + xv4.z*n.z + xv4.w*n.w;
      n = nt2[k4]; vacc[2] += xv4.x*n.x + xv4.y*n.y + xv4.z*n.z + xv4.w*n.w;
      n = nt3[k4]; vacc[3] += xv4.x*n.x + xv4.y*n.y + xv4.z*n.z + xv4.w*n.w;
      n = nt4[k4]; vacc[4] += xv4.x*n.x + xv4.y*n.y + xv4.z*n.z + xv4.w*n.w;
      n = nt5[k4]; vacc[5] += xv4.x*n.x + xv4.y*n.y + xv4.z*n.z + xv4.w*n.w;
    }
    // write V cols 64..191 (j=2..5) to global for cluster exchange
    Vbuf[(rowbase + a) * 128 + lane +  0] = vacc[2];
    Vbuf[(rowbase + a) * 128 + lane + 32] = vacc[3];
    Vbuf[(rowbase + a) * 128 + lane + 64] = vacc[4];
    Vbuf[(rowbase + a) * 128 + lane + 96] = vacc[5];
    cluster_sync_fence();
    // stage full Vc (64 rows x 128) into shared
    for (int i = tid; i < 8192; i += 256) Vcs[i] = Vbuf[i];
    __syncthreads();
    // corr[a][b] = sum_{u<64} LP[a][u]*Vcs[u][b] + LP[a][64+u]*Vcs[u][64+b]
    float c0 = 0.f, c1 = 0.f;
#pragma unroll 8
    for (int u = 0; u < 64; u++) {
      float lpA = LPs[a * 128 + u];
      float lpB = LPs[a * 128 + 64 + u];
      const float* vr = Vcs + u * 128;
      c0 += lpA * vr[lane]      + lpB * vr[64 + lane];
      c1 += lpA * vr[lane + 32] + lpB * vr[96 + lane];
    }
    float xn0 = x0v0 - LMBDA * (vacc[0] + c0);
    float xn1 = x0v1 - LMBDA * (vacc[1] + c1);
    if (it == NITER - 1) {
      outp[(rowbase + a) * 64 + lane]      = xn0;
      outp[(rowbase + a) * 64 + lane + 32] = xn1;
    } else {
      __syncthreads();           // everyone done reading Xs/Vcs
      Xs[a * SH2 + lane]      = xn0;
      Xs[a * SH2 + lane + 32] = xn1;
      __syncthreads();
    }
  }
}

// ---------------- launch ----------------
extern "C" void kernel_launch(void* const* d_in, const int* in_sizes, int n_in,
                              void* d_out, int out_size) {
  const float* fx = (const float*)d_in[0];   // [1,5000,256]
  const float* fy = (const float*)d_in[1];   // [1,5000,256]
  const float* ex = (const float*)d_in[2];   // [1,64]
  const float* ey = (const float*)d_in[3];   // [1,64]
  const float* tx = (const float*)d_in[4];   // [1,64,5000]
  const float* ty = (const float*)d_in[5];   // [1,64,5000]
  const float* sx = (const float*)d_in[6];   // [1,64,64]
  const float* sy = (const float*)d_in[7];   // [1,64,64]
  float* out = (float*)d_out;                // [1,64,64] float32

  zero_kernel<<<32, 256>>>();
  work_kernel<<<203, 256>>>(fx, fy, tx, ty, sx, sy, ey);
  solve_kernel<<<8, 256>>>(ex, out);
}

// round 15
// speedup vs baseline: 1.6702x; 1.0057x over previous
#include <cuda_runtime.h>
#include <math.h>

#define KD 64
#define MDIM 256
#define VDIM 5000
#define LMBDA 0.001f
#define NITER 6
#define VCHUNK 200
#define SH2 68     // staging stride (floats)

// ---------------- device scratch ----------------
__device__ float g_AP[2][KD * MDIM];     // [0]=A=tx@fx, [1]=Py=ty@fy
__device__ float g_S[KD * KD];           // inv(sx)
__device__ float g_Sy[KD * KD];          // inv(sy)
__device__ float g_H[KD * KD];           // sy^T sy
__device__ float g_G[KD * KD];           // A A^T
__device__ float g_T1[KD * KD];          // Py A^T
__device__ float g_Mcat[KD * 192];       // [M2 | M1 | M0] (each symmetric)
__device__ float g_NT[192 * KD];         // NT[c][k] = Ncat[k][c], Ncat=[N2|N1|N0]
__device__ float g_Hinv[KD * KD];
__device__ float g_Ginv[KD * KD];
__device__ float g_HL[KD * KD];          // H ly + ly H   (symmetric)
__device__ float g_LHL[KD * KD];         // ly H ly       (symmetric)
__device__ float g_LP[KD * 128];         // [-Hinv HL | Hinv LHL]
__device__ float g_X0[KD * KD];
__device__ float g_Vd[2][KD * 128];      // double-buffered V cols 64..191

// ---------------- sync ----------------
__device__ __forceinline__ void cluster_sync_fence() {
  __threadfence();
  asm volatile("barrier.cluster.arrive.aligned;" ::: "memory");
  asm volatile("barrier.cluster.wait.aligned;" ::: "memory");
}

// ---------------- helpers ----------------

// C[a0..a0+15][0..63] = scale * sum_k P[a][k]*Q[b][k]; strides multiples of 4.
// Requires blockDim.x == 256.
__device__ __forceinline__ void mm_nt_16(
    const float* __restrict__ P, int ldp,
    const float* __restrict__ Q, int ldq,
    int Klen, float* __restrict__ C, int ldc, int a0, float scale) {
  const int tid = threadIdx.x;
  const int a = a0 + (tid >> 4);
  const int b0 = (tid & 15) << 2;
  float acc0 = 0.f, acc1 = 0.f, acc2 = 0.f, acc3 = 0.f;
  const float4* Pr = (const float4*)(P + a * ldp);
  const float4* Q0 = (const float4*)(Q + (b0 + 0) * ldq);
  const float4* Q1 = (const float4*)(Q + (b0 + 1) * ldq);
  const float4* Q2 = (const float4*)(Q + (b0 + 2) * ldq);
  const float4* Q3 = (const float4*)(Q + (b0 + 3) * ldq);
  const int k4 = Klen >> 2;
#pragma unroll 4
  for (int k = 0; k < k4; k++) {
    float4 av = Pr[k];
    float4 bv;
    bv = Q0[k]; acc0 += av.x * bv.x + av.y * bv.y + av.z * bv.z + av.w * bv.w;
    bv = Q1[k]; acc1 += av.x * bv.x + av.y * bv.y + av.z * bv.z + av.w * bv.w;
    bv = Q2[k]; acc2 += av.x * bv.x + av.y * bv.y + av.z * bv.z + av.w * bv.w;
    bv = Q3[k]; acc3 += av.x * bv.x + av.y * bv.y + av.z * bv.z + av.w * bv.w;
  }
  float* Cr = C + a * ldc + b0;
  Cr[0] = acc0 * scale; Cr[1] = acc1 * scale;
  Cr[2] = acc2 * scale; Cr[3] = acc3 * scale;
}

// Register-resident pivot-free Gauss-Jordan inverse of a 64x64.
// 256 threads: thread owns CONTIGUOUS rows [16*r0, 16*r0+16) at column c=tid&63.
// Pivot loop unrolled x16 so every register-array index is compile-time static.
__device__ void gj_inverse_reg(const float* __restrict__ in,
                               float* __restrict__ out) {
  __shared__ __align__(16) float prow[2][64];
  __shared__ __align__(16) float pcol[2][64];
  const int tid = threadIdx.x;
  const int r0 = tid >> 6;        // 0..3 -> rows 16*r0 .. 16*r0+15
  const int c  = tid & 63;
  float v[16];
#pragma unroll
  for (int q = 0; q < 16; q++) v[q] = in[(r0 * 16 + q) * 64 + c];
  if (c == 0) {
#pragma unroll
    for (int q = 0; q < 16; q++) pcol[0][r0 * 16 + q] = v[q];
  }
  if (r0 == 0) prow[0][c] = v[0];
  __syncthreads();
  for (int po = 0; po < 4; po++) {
#pragma unroll
    for (int j = 0; j < 16; j++) {
      const int p = po * 16 + j;
      const int cur = p & 1, nxt = cur ^ 1;
      const float piv = prow[cur][p];
      const float dinv = 1.0f / piv;
      const float prc = prow[cur][c] * dinv;
      const bool cp = (c == p);
      const bool rown = (r0 == po);
      const float w = cp ? dinv : prc;
      float pc[16];
      {
        const float4* pcb = (const float4*)&pcol[cur][r0 * 16];
        float4 t0 = pcb[0], t1 = pcb[1], t2 = pcb[2], t3 = pcb[3];
        pc[0]=t0.x; pc[1]=t0.y; pc[2]=t0.z; pc[3]=t0.w;
        pc[4]=t1.x; pc[5]=t1.y; pc[6]=t1.z; pc[7]=t1.w;
        pc[8]=t2.x; pc[9]=t2.y; pc[10]=t2.z; pc[11]=t2.w;
        pc[12]=t3.x; pc[13]=t3.y; pc[14]=t3.z; pc[15]=t3.w;
      }
#pragma unroll
      for (int q = 0; q < 16; q++) {
        float base = cp ? 0.0f : v[q];
        v[q] = fmaf(-pc[q], w, base);
      }
      if (rown) v[j] = cp ? dinv : prc;
      if (p < 63) {
        const int pn = p + 1;
        if (c == pn) {
#pragma unroll
          for (int q = 0; q < 16; q++) pcol[nxt][r0 * 16 + q] = v[q];
        }
        if (r0 == (pn >> 4)) prow[nxt][c] = v[(j + 1) & 15];
      }
      __syncthreads();
    }
  }
#pragma unroll
  for (int q = 0; q < 16; q++) out[(r0 * 16 + q) * 64 + c] = v[q];
}

// ---------------- kernel 0: zero split-K accumulators ----------------
__global__ void zero_kernel() {
  int i = blockIdx.x * 256 + threadIdx.x;
  ((float4*)g_AP)[i] = make_float4(0.f, 0.f, 0.f, 0.f);
}

// ---------------- kernel 1: gemm + independent prep blocks ----------------
// bid<200: split-K gemm. bid==200: S=inv(sx) + Mcat. 201: Sy=inv(sy) + Hinv.
// 202: H/HL/LHL.
__global__ void __launch_bounds__(256, 2)
work_kernel(const float* __restrict__ fx, const float* __restrict__ fy,
            const float* __restrict__ tx, const float* __restrict__ ty,
            const float* __restrict__ sx, const float* __restrict__ sy,
            const float* __restrict__ ex, const float* __restrict__ ey) {
  __shared__ __align__(16) float shw[64 * SH2];   // 17KB multi-use
  const int bid = blockIdx.x;
  const int tid = threadIdx.x;

  if (bid < 200) {
    float* Ws = shw;          // [8][64]
    float* Fs = shw + 512;    // [8][64]
    const int mat = bid / 100;
    const int r   = bid % 100;
    const int mt  = r & 3;
    const int vs  = r >> 2;
    const float* __restrict__ F  = mat ? fy : fx;   // [VDIM][MDIM]
    const float* __restrict__ Wm = mat ? ty : tx;   // [KD][VDIM]
    float* out = g_AP[mat];
    const int m0 = mt * 64;
    const int v0 = vs * VCHUNK;
    const int kkA = tid & 7,  rowA = tid >> 3;
    const int kk2A = tid >> 6, colA = tid & 63;
    const int idxB = tid + 256;
    const int kkB = idxB & 7,  rowB = idxB >> 3;
    const int kk2B = idxB >> 6, colB = idxB & 63;
    const float* WA = Wm + rowA * VDIM + kkA;
    const float* WB = Wm + rowB * VDIM + kkB;
    const float* FA = F + kk2A * MDIM + m0 + colA;
    const float* FB = F + kk2B * MDIM + m0 + colB;
    const int tr = (tid >> 4) << 2;
    const int tc = (tid & 15) << 2;
    float acc[4][4];
#pragma unroll
    for (int i = 0; i < 4; i++)
#pragma unroll
      for (int j = 0; j < 4; j++) acc[i][j] = 0.f;

    float w0 = WA[v0], w1 = WB[v0];
    float f0 = FA[v0 * MDIM], f1 = FB[v0 * MDIM];
    for (int vv = v0; vv < v0 + VCHUNK; vv += 8) {
      Ws[kkA * 64 + rowA] = w0;
      Ws[kkB * 64 + rowB] = w1;
      Fs[kk2A * 64 + colA] = f0;
      Fs[kk2B * 64 + colB] = f1;
      __syncthreads();
      const int nv = vv + 8;
      if (nv < v0 + VCHUNK) {
        w0 = WA[nv]; w1 = WB[nv];
        f0 = FA[nv * MDIM]; f1 = FB[nv * MDIM];
      }
#pragma unroll
      for (int kk = 0; kk < 8; kk++) {
        float4 av = *(const float4*)&Ws[kk * 64 + tr];
        float4 bv = *(const float4*)&Fs[kk * 64 + tc];
        acc[0][0] += av.x * bv.x; acc[0][1] += av.x * bv.y; acc[0][2] += av.x * bv.z; acc[0][3] += av.x * bv.w;
        acc[1][0] += av.y * bv.x; acc[1][1] += av.y * bv.y; acc[1][2] += av.y * bv.z; acc[1][3] += av.y * bv.w;
        acc[2][0] += av.z * bv.x; acc[2][1] += av.z * bv.y; acc[2][2] += av.z * bv.z; acc[2][3] += av.z * bv.w;
        acc[3][0] += av.w * bv.x; acc[3][1] += av.w * bv.y; acc[3][2] += av.w * bv.z; acc[3][3] += av.w * bv.w;
      }
      __syncthreads();
    }
#pragma unroll
    for (int i = 0; i < 4; i++)
#pragma unroll
      for (int j = 0; j < 4; j++)
        atomicAdd(&out[(tr + i) * MDIM + m0 + tc + j], acc[i][j]);

  } else if (bid == 200) {
    // S = inv(sx), then M_j = S^T lx^j S (sqrt-weighted NT form), j=2,1,0
    gj_inverse_reg(sx, g_S);
    __syncthreads();
    for (int t = 0; t < 3; t++) {
      const int jc = t * 64;
      for (int i = tid; i < 4096; i += 256) {
        int a = i >> 6, ii = i & 63;
        float w = (t == 0) ? ex[ii] : ((t == 1) ? sqrtf(ex[ii]) : 1.0f);
        shw[a * SH2 + ii] = g_S[ii * 64 + a] * w;
      }
      __syncthreads();
      for (int a0 = 0; a0 < 64; a0 += 16)
        mm_nt_16(shw, SH2, shw, SH2, 64, g_Mcat + jc, 192, a0, 1.0f);
      __syncthreads();
    }
  } else if (bid == 201) {
    // Sy = inv(sy), then Hinv = Sy Sy^T
    gj_inverse_reg(sy, g_Sy);
    __syncthreads();
    for (int a0 = 0; a0 < 64; a0 += 16)
      mm_nt_16(g_Sy, 64, g_Sy, 64, 64, g_Hinv, 64, a0, 1.0f);
  } else {
    // H = sy^T sy; HL = H.*(ey_r+ey_c); LHL = ey_r.*H.*ey_c
    for (int i = tid; i < 4096; i += 256) {
      int a = i >> 6, rr = i & 63;
      shw[a * SH2 + rr] = sy[rr * 64 + a];
    }
    __syncthreads();
    for (int a0 = 0; a0 < 64; a0 += 16)
      mm_nt_16(shw, SH2, shw, SH2, 64, g_H, 64, a0, 1.0f);
    __syncthreads();
    for (int i = tid; i < 4096; i += 256) {
      int rr = i >> 6, cc = i & 63;
      float h = g_H[i];
      g_HL[i]  = h * (ey[rr] + ey[cc]);
      g_LHL[i] = ey[rr] * h * ey[cc];
    }
  }
}

// ---------------- kernel 2: solve (8-CTA cluster) ----------------
__global__ void __cluster_dims__(8, 1, 1) __launch_bounds__(256, 1)
solve_kernel(float* __restrict__ outp) {
  __shared__ __align__(16) float sh[11776];   // 47KB multi-use
  float* Qs = sh + 4352;                      // Mcat slab stage [64][SH2]
  const int rk = blockIdx.x;       // cluster rank 0..7
  const int tid = threadIdx.x;

  // ---- Phase A: one G/T1 slab + one LP slab per rank; prestage Mcat ----
  if (rk < 4) {
    mm_nt_16(g_AP[0], MDIM, g_AP[0], MDIM, MDIM, g_G, 64, rk * 16, 1.0f);
  } else {
    mm_nt_16(g_AP[1], MDIM, g_AP[0], MDIM, MDIM, g_T1, 64, (rk - 4) * 16, 1.0f);
  }
  {
    // LP: rank r -> half t=r>>2, slab a0=(r&3)*16. HL/LHL symmetric -> NT ok.
    const int t = rk >> 2;
    const int a0 = (rk & 3) * 16;
    const float* Q = t ? g_LHL : g_HL;
    const float scale = t ? 1.0f : -1.0f;
    const int off = t ? 64 : 0;
    mm_nt_16(g_Hinv, 64, Q, 64, 64, g_LP + off, 128, a0, scale);
  }
  if (rk < 6) {
    // prestage Mcat slab t = rk>>1 (symmetric slab: Qs[b][k] = Mcat[b][jc+k])
    const int jc = (rk >> 1) * 64;
    for (int i = tid; i < 4096; i += 256) {
      int b = i >> 6, k = i & 63;
      Qs[b * SH2 + k] = g_Mcat[b * 192 + jc + k];
    }
  }
  cluster_sync_fence();

  // ---- Phase B: Ginv = inv(G) on rank 0 ----
  if (rk == 0) gj_inverse_reg(g_G, g_Ginv);
  cluster_sync_fence();

  // ---- Phase C: stage GinvT; ranks 0-5: 2 NT units; ranks 6-7: 2 X0 units ----
  for (int i = tid; i < 4096; i += 256) {
    int b = i >> 6, u = i & 63;
    sh[b * SH2 + u] = g_Ginv[u * 64 + b];     // GinvT
  }
  __syncthreads();
  if (rk < 6) {
    const int jc = (rk >> 1) * 64;
    const int a0 = (rk & 1) * 32;
    mm_nt_16(sh, SH2, Qs, SH2, 64, g_NT + jc * 64, 64, a0, 1.0f);
    mm_nt_16(sh, SH2, Qs, SH2, 64, g_NT + jc * 64, 64, a0 + 16, 1.0f);
  } else {
    const int base = (rk - 6) * 32;
    mm_nt_16(g_T1, 64, sh, SH2, 64, g_X0, 64, base, 1.0f);
    mm_nt_16(g_T1, 64, sh, SH2, 64, g_X0, 64, base + 16, 1.0f);
  }
  cluster_sync_fence();

  // ---- Phase D: Richardson iterations; CTA owns 8 rows ----
  const int rowbase = rk * 8;
  float* Vcs = sh;                 // [64][128] = 8192 floats
  float* LPs = sh + 8192;          // [8][128]  = 1024 floats
  float* Xs  = sh + 8192 + 1024;   // [8][SH2]  = 544 floats
  for (int i = tid; i < 1024; i += 256)
    LPs[i] = g_LP[(rowbase + (i >> 7)) * 128 + (i & 127)];
  for (int i = tid; i < 512; i += 256) {
    int a = i >> 6, b = i & 63;
    Xs[a * SH2 + b] = g_X0[(rowbase + a) * 64 + b];
  }
  const int a    = tid >> 5;       // 0..7 local row
  const int lane = tid & 31;
  float x0v0 = g_X0[(rowbase + a) * 64 + lane];
  float x0v1 = g_X0[(rowbase + a) * 64 + lane + 32];
  __syncthreads();

  for (int it = 0; it < NITER; it++) {
    float* Vbuf = g_Vd[it & 1];
    // V[a][c] = sum_k Xs[a][k] * NT[c][k], cols c = lane + 32j, j=0..5
    float vacc[6] = {0.f, 0.f, 0.f, 0.f, 0.f, 0.f};
    const float4* xr = (const float4*)(Xs + a * SH2);
    const float4* nt0 = (const float4*)(g_NT + (lane +   0) * 64);
    const float4* nt1 = (const float4*)(g_NT + (lane +  32) * 64);
    const float4* nt2 = (const float4*)(g_NT + (lane +  64) * 64);
    const float4* nt3 = (const float4*)(g_NT + (lane +  96) * 64);
    const float4* nt4 = (const float4*)(g_NT + (lane + 128) * 64);
    const float4* nt5 = (const float4*)(g_NT + (lane + 160) * 64);
#pragma unroll
    for (int k4 = 0; k4 < 16; k4++) {
      float4 xv4 = xr[k4];
      float4 n;
      n = nt0[k4]; vacc[0] += xv4.x*n.x + xv4.y*n.y + xv4.z*n.z + xv4.w*n.w;
      n = nt1[k4]; vacc[1] += xv4.x*n.x + xv4.y*n.y + xv4.z*n.z + xv4.w*n.w;
      n = nt2[k4]; vacc[2] += xv4.x*n.x + xv4.y*n.y + xv4.z*n.z + xv4.w*n.w;
      n = nt3[k4]; vacc[3] += xv4.x*n.x + xv4.y*n.y + xv4.z*n.z + xv4.w*n.w;
      n = nt4[k4]; vacc[4] += xv4.x*n.x + xv4.y*n.y + xv4.z*n.z + xv4.w*n.w;
      n = nt5[k4]; vacc[5] += xv4.x*n.x + xv4.y*n.y + xv4.z*n.z + xv4.w*n.w;
    }
    // write V cols 64..191 (j=2..5) to global for cluster exchange
    Vbuf[(rowbase + a) * 128 + lane +  0] = vacc[2];
    Vbuf[(rowbase + a) * 128 + lane + 32] = vacc[3];
    Vbuf[(rowbase + a) * 128 + lane + 64] = vacc[4];
    Vbuf[(rowbase + a) * 128 + lane + 96] = vacc[5];
    cluster_sync_fence();
    // stage full Vc (64 rows x 128) into shared
    for (int i = tid; i < 8192; i += 256) Vcs[i] = Vbuf[i];
    __syncthreads();
    // corr[a][b] = sum_{u<64} LP[a][u]*Vcs[u][b] + LP[a][64+u]*Vcs[u][64+b]
    float c0 = 0.f, c1 = 0.f;
#pragma unroll 8
    for (int u = 0; u < 64; u++) {
      float lpA = LPs[a * 128 + u];
      float lpB = LPs[a * 128 + 64 + u];
      const float* vr = Vcs + u * 128;
      c0 += lpA * vr[lane]      + lpB * vr[64 + lane];
      c1 += lpA * vr[lane + 32] + lpB * vr[96 + lane];
    }
    float xn0 = x0v0 - LMBDA * (vacc[0] + c0);
    float xn1 = x0v1 - LMBDA * (vacc[1] + c1);
    if (it == NITER - 1) {
      outp[(rowbase + a) * 64 + lane]      = xn0;
      outp[(rowbase + a) * 64 + lane + 32] = xn1;
    } else {
      __syncthreads();           // everyone done reading Xs/Vcs
      Xs[a * SH2 + lane]      = xn0;
      Xs[a * SH2 + lane + 32] = xn1;
      __syncthreads();
    }
  }
}

// ---------------- launch ----------------
extern "C" void kernel_launch(void* const* d_in, const int* in_sizes, int n_in,
                              void* d_out, int out_size) {
  const float* fx = (const float*)d_in[0];   // [1,5000,256]
  const float* fy = (const float*)d_in[1];   // [1,5000,256]
  const float* ex = (const float*)d_in[2];   // [1,64]
  const float* ey = (const float*)d_in[3];   // [1,64]
  const float* tx = (const float*)d_in[4];   // [1,64,5000]
  const float* ty = (const float*)d_in[5];   // [1,64,5000]
  const float* sx = (const float*)d_in[6];   // [1,64,64]
  const float* sy = (const float*)d_in[7];   // [1,64,64]
  float* out = (float*)d_out;                // [1,64,64] float32

  zero_kernel<<<32, 256>>>();
  work_kernel<<<203, 256>>>(fx, fy, tx, ty, sx, sy, ex, ey);
  solve_kernel<<<8, 256>>>(out);
}